// round 14
// baseline (speedup 1.0000x reference)
#include <cuda_runtime.h>
#include <math.h>

typedef unsigned long long u64;
typedef unsigned int u32;

// ---------------- fixed shape: P=4, M=N=8192 --------------------------------
#define CAP 65536
#define QCH 1024   // queries per block (256 thr * 4 qpt)
#define TSL 256    // targets per block (tile = 8KB); divides 8192
#define NRED 256

__device__ float    g_cadT[CAP * 8];   // transformed cad, dup fmt [x,x,y,y,z,z,h,h], h=|v|^2/2
__device__ float    g_camT[CAP * 8];   // cam, dup fmt
__device__ float4   g_cadQ[CAP];       // transformed cad, query fmt (x,y,z,|v|^2)
__device__ float4   g_camQ[CAP];
__device__ unsigned g_minbuf[2 * CAP]; // per-(dir,p,query) min d2 as uint bits
__device__ float    g_partial[NRED];
__device__ unsigned g_done;

// ---------------- f32x2 helpers ---------------------------------------------
__device__ __forceinline__ u64 pack2(float lo, float hi) {
    u64 r; asm("mov.b64 %0, {%1, %2};" : "=l"(r) : "f"(lo), "f"(hi)); return r;
}
__device__ __forceinline__ void unpack2(u64 v, float& lo, float& hi) {
    asm("mov.b64 {%0, %1}, %2;" : "=f"(lo), "=f"(hi) : "l"(v));
}
__device__ __forceinline__ u64 fma2(u64 a, u64 b, u64 c) {
    u64 d; asm("fma.rn.f32x2 %0, %1, %2, %3;" : "=l"(d) : "l"(a), "l"(b), "l"(c)); return d;
}
__device__ __forceinline__ void redg_min(unsigned* addr, unsigned v) {
    asm volatile("red.global.min.u32 [%0], %1;" :: "l"(addr), "r"(v) : "memory");
}

// ---------------- transform builder ------------------------------------------
__device__ __forceinline__ void make_tf(const float* quat, const float* tra, int p, float tf[12]) {
    float a = quat[4*p], b = quat[4*p+1], c = quat[4*p+2], d = quat[4*p+3];
    float inv = rsqrtf(a*a + b*b + c*c + d*d);
    a *= inv; b *= inv; c *= inv; d *= inv;
    tf[0] = 1.f - 2.f*(c*c + d*d); tf[1] = 2.f*(b*c - a*d);        tf[2]  = 2.f*(a*c + b*d);        tf[3]  = tra[3*p+0];
    tf[4] = 2.f*(b*c + a*d);       tf[5] = 1.f - 2.f*(b*b + d*d);  tf[6]  = 2.f*(c*d - a*b);        tf[7]  = tra[3*p+1];
    tf[8] = 2.f*(b*d - a*c);       tf[9] = 2.f*(a*b + c*d);        tf[10] = 1.f - 2.f*(b*b + c*c);  tf[11] = tra[3*p+2];
}

// ---------------- launch 0: transforms + point buffers + minbuf -------------
__global__ void k_prep(const float* __restrict__ cad, const float* __restrict__ cam,
                       const float* __restrict__ quat, const float* __restrict__ tra,
                       float* __restrict__ out, int P, int M, int N, int total, int write_out) {
    int idx = blockIdx.x * blockDim.x + threadIdx.x;
    if (idx == 0) g_done = 0u;
    if (blockIdx.x == 0 && threadIdx.x < P && write_out) {
        float tf[12]; make_tf(quat, tra, threadIdx.x, tf);
        float* o = out + 1 + threadIdx.x * 16;
#pragma unroll
        for (int i = 0; i < 12; i++) o[i] = tf[i];
        o[12] = 0.f; o[13] = 0.f; o[14] = 0.f; o[15] = 1.f;
    }
    if (idx >= total) return;
    g_minbuf[idx] = 0x7f800000u;  // +inf

    float vx, vy, vz;
    if (idx < P * M) {
        int p = idx / M;
        float tf[12]; make_tf(quat, tra, p, tf);
        const float* pt = cad + (size_t)idx * 3;
        float x = pt[0], y = pt[1], z = pt[2];
        vx = tf[0]*x + tf[1]*y + tf[2]*z  + tf[3];
        vy = tf[4]*x + tf[5]*y + tf[6]*z  + tf[7];
        vz = tf[8]*x + tf[9]*y + tf[10]*z + tf[11];
        float n2 = vx*vx + vy*vy + vz*vz;
        float* T = g_cadT + (size_t)idx * 8;
        T[0] = vx; T[1] = vx; T[2] = vy; T[3] = vy;
        T[4] = vz; T[5] = vz; T[6] = 0.5f * n2; T[7] = 0.5f * n2;
        g_cadQ[idx] = make_float4(vx, vy, vz, n2);
    } else {
        int j = idx - P * M;
        const float* pt = cam + (size_t)j * 3;
        vx = pt[0]; vy = pt[1]; vz = pt[2];
        float n2 = vx*vx + vy*vy + vz*vz;
        float* T = g_camT + (size_t)j * 8;
        T[0] = vx; T[1] = vx; T[2] = vy; T[3] = vy;
        T[4] = vz; T[5] = vz; T[6] = 0.5f * n2; T[7] = 0.5f * n2;
        g_camQ[j] = make_float4(vx, vy, vz, n2);
    }
}

// ---------------- launch 1 (hot): chamfer, one item per block, occ 4 --------
__global__ void __launch_bounds__(256, 4) k_chamfer(int P, int M, int N,
                                                    int qcA, int tsA, int qcB, int tsB) {
    __shared__ __align__(16) float tile[TSL * 8];   // 8KB

    const int tid = threadIdx.x;
    const float INF = __int_as_float(0x7f800000);
    const int itemsA = P * qcA * tsA;
    const int item = blockIdx.x;

    int p, qc, sl, minoff;
    const float4* Q;
    const float*  T;
    if (item < itemsA) {
        p = item / (qcA * tsA); int r = item % (qcA * tsA); qc = r / tsA; sl = r % tsA;
        Q = g_cadQ + (size_t)p * M;
        T = g_camT + (size_t)p * N * 8;
        minoff = p * M;
    } else {
        int b1 = item - itemsA;
        p = b1 / (qcB * tsB); int r = b1 % (qcB * tsB); qc = r / tsB; sl = r % tsB;
        Q = g_camQ + (size_t)p * N;
        T = g_cadT + (size_t)p * M * 8;
        minoff = P * M + p * N;
    }

    // ---- cooperative tile load: 512 float4 = full 8KB ----
    {
        const float4* src = (const float4*)(T + (size_t)sl * TSL * 8);
        ((float4*)tile)[tid]       = src[tid];
        ((float4*)tile)[tid + 256] = src[tid + 256];
    }

    // ---- 4 query points per thread (2 packed pairs); no bounds checks ----
    u64 qnx[2], qny[2], qnz[2];
    float mn0[2], mn1[2], x2a[2], x2b[2];
    int base = qc * QCH + tid;
#pragma unroll
    for (int k = 0; k < 2; k++) {
        float4 A = Q[base + (2 * k) * 256];
        float4 B = Q[base + (2 * k + 1) * 256];
        qnx[k] = pack2(-A.x, -B.x);
        qny[k] = pack2(-A.y, -B.y);
        qnz[k] = pack2(-A.z, -B.z);
        x2a[k] = A.w; x2b[k] = B.w;
        mn0[k] = INF; mn1[k] = INF;
    }
    __syncthreads();

    // ---- main loop: 4 targets x 4 queries per iteration ----
#pragma unroll 2
    for (int j = 0; j < TSL; j += 4) {
        const float* tp = tile + j * 8;
        ulonglong2 a0 = *(const ulonglong2*)(tp);
        ulonglong2 a1 = *(const ulonglong2*)(tp + 4);
        ulonglong2 b0 = *(const ulonglong2*)(tp + 8);
        ulonglong2 b1 = *(const ulonglong2*)(tp + 12);
        ulonglong2 c0 = *(const ulonglong2*)(tp + 16);
        ulonglong2 c1 = *(const ulonglong2*)(tp + 20);
        ulonglong2 d0 = *(const ulonglong2*)(tp + 24);
        ulonglong2 d1 = *(const ulonglong2*)(tp + 28);
#pragma unroll
        for (int k = 0; k < 2; k++) {
            u64 gA = fma2(qnx[k], a0.x, a1.y);
            u64 gB = fma2(qnx[k], b0.x, b1.y);
            u64 gC = fma2(qnx[k], c0.x, c1.y);
            u64 gD = fma2(qnx[k], d0.x, d1.y);
            gA = fma2(qny[k], a0.y, gA);
            gB = fma2(qny[k], b0.y, gB);
            gC = fma2(qny[k], c0.y, gC);
            gD = fma2(qny[k], d0.y, gD);
            gA = fma2(qnz[k], a1.x, gA);
            gB = fma2(qnz[k], b1.x, gB);
            gC = fma2(qnz[k], c1.x, gC);
            gD = fma2(qnz[k], d1.x, gD);
            float alo, ahi, blo, bhi, clo, chi, dlo, dhi;
            unpack2(gA, alo, ahi); unpack2(gB, blo, bhi);
            unpack2(gC, clo, chi); unpack2(gD, dlo, dhi);
            float lo01 = fminf(alo, blo), lo23 = fminf(clo, dlo);
            float hi01 = fminf(ahi, bhi), hi23 = fminf(chi, dhi);
            mn0[k] = fminf(mn0[k], fminf(lo01, lo23));
            mn1[k] = fminf(mn1[k], fminf(hi01, hi23));
        }
    }

    // ---- combine across slices: d2 = 2*g + |q|^2 (>=0), fire-and-forget REDG ----
#pragma unroll
    for (int k = 0; k < 2; k++) {
        float da = fmaxf(fmaf(2.f, mn0[k], x2a[k]), 0.f);
        float db = fmaxf(fmaf(2.f, mn1[k], x2b[k]), 0.f);
        redg_min(g_minbuf + minoff + base + (2 * k) * 256,     __float_as_uint(da));
        redg_min(g_minbuf + minoff + base + (2 * k + 1) * 256, __float_as_uint(db));
    }
}

// ---------------- launch 2: weighted sqrt-sum + fused final (last block) ----
__global__ void k_red(const float* __restrict__ w, float* __restrict__ out,
                      int P, int M, int N) {
    __shared__ float sh[256];
    __shared__ bool last;
    int e = blockIdx.x * 256 + threadIdx.x;   // exactly one element per thread
    int p; float invc;
    if (e < P * M) { p = e / M; invc = 1.0f / (float)M; }
    else           { p = (e - P * M) / N; invc = 1.0f / (float)N; }
    sh[threadIdx.x] = w[p] * invc * sqrtf(__uint_as_float(g_minbuf[e]));
    __syncthreads();
    for (int o = 128; o > 0; o >>= 1) {
        if (threadIdx.x < o) sh[threadIdx.x] += sh[threadIdx.x + o];
        __syncthreads();
    }
    if (threadIdx.x == 0) {
        g_partial[blockIdx.x] = sh[0];
        __threadfence();
        last = (atomicAdd(&g_done, 1u) == NRED - 1);
    }
    __syncthreads();
    if (last) {   // final deterministic tree over 256 partials
        sh[threadIdx.x] = g_partial[threadIdx.x];
        __syncthreads();
        for (int o = 128; o > 0; o >>= 1) {
            if (threadIdx.x < o) sh[threadIdx.x] += sh[threadIdx.x + o];
            __syncthreads();
        }
        if (threadIdx.x == 0) out[0] = sh[0];
    }
}

// ---------------- launcher ----------------------------------------------------
extern "C" void kernel_launch(void* const* d_in, const int* in_sizes, int n_in,
                              void* d_out, int out_size) {
    const float* cam  = (const float*)d_in[0];  // (P,N,3)
    const float* cad  = (const float*)d_in[1];  // (P,M,3)
    const float* wgt  = (const float*)d_in[2];  // (P,)
    const float* quat = (const float*)d_in[3];  // (P,4)
    const float* tra  = (const float*)d_in[4];  // (P,3,1)
    float* out = (float*)d_out;

    int P = in_sizes[2];
    int N = in_sizes[0] / (3 * P);
    int M = in_sizes[1] / (3 * P);
    int write_out = (out_size >= 1 + 16 * P) ? 1 : 0;

    int total = P * (M + N);
    k_prep<<<(total + 255) / 256, 256>>>(cad, cam, quat, tra, out, P, M, N, total, write_out); // 0

    int qcA = (M + QCH - 1) / QCH, tsA = (N + TSL - 1) / TSL;
    int qcB = (N + QCH - 1) / QCH, tsB = (M + TSL - 1) / TSL;
    int items = P * (qcA * tsA + qcB * tsB);   // 2048
    k_chamfer<<<items, 256>>>(P, M, N, qcA, tsA, qcB, tsB);                                    // 1 (hot)

    k_red<<<NRED, 256>>>(wgt, out, P, M, N);                                                   // 2
}

// round 15
// speedup vs baseline: 1.0788x; 1.0788x over previous
#include <cuda_runtime.h>
#include <math.h>

typedef unsigned long long u64;
typedef unsigned int u32;

// ---------------- fixed shape: P=4, M=N=8192 --------------------------------
#define CAP 65536
#define QCH 1024   // queries per block (256 thr * 4 qpt)
#define TSL 128    // targets per block (tile = 4KB); divides 8192
#define NRED 256

__device__ float    g_cadT[CAP * 8];   // transformed cad, dup fmt [x,x,y,y,z,z,h,h], h=|v|^2/2
__device__ float    g_camT[CAP * 8];   // cam, dup fmt
__device__ float4   g_cadQ[CAP];       // transformed cad, query fmt (x,y,z,|v|^2)
__device__ float4   g_camQ[CAP];
__device__ unsigned g_minbuf[2 * CAP]; // per-(dir,p,query) min d2 as uint bits
__device__ float    g_partial[NRED];
__device__ unsigned g_done;

// ---------------- f32x2 helpers ---------------------------------------------
__device__ __forceinline__ u64 pack2(float lo, float hi) {
    u64 r; asm("mov.b64 %0, {%1, %2};" : "=l"(r) : "f"(lo), "f"(hi)); return r;
}
__device__ __forceinline__ void unpack2(u64 v, float& lo, float& hi) {
    asm("mov.b64 {%0, %1}, %2;" : "=f"(lo), "=f"(hi) : "l"(v));
}
__device__ __forceinline__ u64 fma2(u64 a, u64 b, u64 c) {
    u64 d; asm("fma.rn.f32x2 %0, %1, %2, %3;" : "=l"(d) : "l"(a), "l"(b), "l"(c)); return d;
}
__device__ __forceinline__ void redg_min(unsigned* addr, unsigned v) {
    asm volatile("red.global.min.u32 [%0], %1;" :: "l"(addr), "r"(v) : "memory");
}

// ---------------- transform builder ------------------------------------------
__device__ __forceinline__ void make_tf(const float* quat, const float* tra, int p, float tf[12]) {
    float a = quat[4*p], b = quat[4*p+1], c = quat[4*p+2], d = quat[4*p+3];
    float inv = rsqrtf(a*a + b*b + c*c + d*d);
    a *= inv; b *= inv; c *= inv; d *= inv;
    tf[0] = 1.f - 2.f*(c*c + d*d); tf[1] = 2.f*(b*c - a*d);        tf[2]  = 2.f*(a*c + b*d);        tf[3]  = tra[3*p+0];
    tf[4] = 2.f*(b*c + a*d);       tf[5] = 1.f - 2.f*(b*b + d*d);  tf[6]  = 2.f*(c*d - a*b);        tf[7]  = tra[3*p+1];
    tf[8] = 2.f*(b*d - a*c);       tf[9] = 2.f*(a*b + c*d);        tf[10] = 1.f - 2.f*(b*b + c*c);  tf[11] = tra[3*p+2];
}

// ---------------- launch 0: transforms + point buffers + minbuf -------------
__global__ void k_prep(const float* __restrict__ cad, const float* __restrict__ cam,
                       const float* __restrict__ quat, const float* __restrict__ tra,
                       float* __restrict__ out, int P, int M, int N, int total, int write_out) {
    int idx = blockIdx.x * blockDim.x + threadIdx.x;
    if (idx == 0) g_done = 0u;
    if (blockIdx.x == 0 && threadIdx.x < P && write_out) {
        float tf[12]; make_tf(quat, tra, threadIdx.x, tf);
        float* o = out + 1 + threadIdx.x * 16;
#pragma unroll
        for (int i = 0; i < 12; i++) o[i] = tf[i];
        o[12] = 0.f; o[13] = 0.f; o[14] = 0.f; o[15] = 1.f;
    }
    if (idx >= total) return;
    g_minbuf[idx] = 0x7f800000u;  // +inf

    float vx, vy, vz;
    float* T;
    if (idx < P * M) {
        int p = idx / M;
        float tf[12]; make_tf(quat, tra, p, tf);
        const float* pt = cad + (size_t)idx * 3;
        float x = pt[0], y = pt[1], z = pt[2];
        vx = tf[0]*x + tf[1]*y + tf[2]*z  + tf[3];
        vy = tf[4]*x + tf[5]*y + tf[6]*z  + tf[7];
        vz = tf[8]*x + tf[9]*y + tf[10]*z + tf[11];
        T = g_cadT + (size_t)idx * 8;
    } else {
        int j = idx - P * M;
        const float* pt = cam + (size_t)j * 3;
        vx = pt[0]; vy = pt[1]; vz = pt[2];
        T = g_camT + (size_t)j * 8;
    }
    float n2 = vx*vx + vy*vy + vz*vz;
    float h = 0.5f * n2;
    ((float4*)T)[0] = make_float4(vx, vx, vy, vy);
    ((float4*)T)[1] = make_float4(vz, vz, h, h);
    if (idx < P * M) g_cadQ[idx]         = make_float4(vx, vy, vz, n2);
    else             g_camQ[idx - P * M] = make_float4(vx, vy, vz, n2);
}

// ---------------- launch 1 (hot): chamfer, one item per block, occ 4 --------
__global__ void __launch_bounds__(256, 4) k_chamfer(int P, int M, int N,
                                                    int qcA, int tsA, int qcB, int tsB) {
    __shared__ __align__(16) float tile[TSL * 8];   // 4KB

    const int tid = threadIdx.x;
    const float INF = __int_as_float(0x7f800000);
    const int itemsA = P * qcA * tsA;
    const int item = blockIdx.x;

    int p, qc, sl, minoff;
    const float4* Q;
    const float*  T;
    if (item < itemsA) {
        p = item / (qcA * tsA); int r = item % (qcA * tsA); qc = r / tsA; sl = r % tsA;
        Q = g_cadQ + (size_t)p * M;
        T = g_camT + (size_t)p * N * 8;
        minoff = p * M;
    } else {
        int b1 = item - itemsA;
        p = b1 / (qcB * tsB); int r = b1 % (qcB * tsB); qc = r / tsB; sl = r % tsB;
        Q = g_camQ + (size_t)p * N;
        T = g_cadT + (size_t)p * M * 8;
        minoff = P * M + p * N;
    }

    // ---- cooperative tile load: 256 float4 = full 4KB ----
    ((float4*)tile)[tid] = ((const float4*)(T + (size_t)sl * TSL * 8))[tid];

    // ---- 4 query points per thread (2 packed pairs); no bounds checks ----
    u64 qnx[2], qny[2], qnz[2];
    float mn0[2], mn1[2], x2a[2], x2b[2];
    int base = qc * QCH + tid;
#pragma unroll
    for (int k = 0; k < 2; k++) {
        float4 A = Q[base + (2 * k) * 256];
        float4 B = Q[base + (2 * k + 1) * 256];
        qnx[k] = pack2(-A.x, -B.x);
        qny[k] = pack2(-A.y, -B.y);
        qnz[k] = pack2(-A.z, -B.z);
        x2a[k] = A.w; x2b[k] = B.w;
        mn0[k] = INF; mn1[k] = INF;
    }
    __syncthreads();

    // ---- main loop: 4 targets x 4 queries per iteration ----
#pragma unroll 2
    for (int j = 0; j < TSL; j += 4) {
        const float* tp = tile + j * 8;
        ulonglong2 a0 = *(const ulonglong2*)(tp);
        ulonglong2 a1 = *(const ulonglong2*)(tp + 4);
        ulonglong2 b0 = *(const ulonglong2*)(tp + 8);
        ulonglong2 b1 = *(const ulonglong2*)(tp + 12);
        ulonglong2 c0 = *(const ulonglong2*)(tp + 16);
        ulonglong2 c1 = *(const ulonglong2*)(tp + 20);
        ulonglong2 d0 = *(const ulonglong2*)(tp + 24);
        ulonglong2 d1 = *(const ulonglong2*)(tp + 28);
#pragma unroll
        for (int k = 0; k < 2; k++) {
            u64 gA = fma2(qnx[k], a0.x, a1.y);
            u64 gB = fma2(qnx[k], b0.x, b1.y);
            u64 gC = fma2(qnx[k], c0.x, c1.y);
            u64 gD = fma2(qnx[k], d0.x, d1.y);
            gA = fma2(qny[k], a0.y, gA);
            gB = fma2(qny[k], b0.y, gB);
            gC = fma2(qny[k], c0.y, gC);
            gD = fma2(qny[k], d0.y, gD);
            gA = fma2(qnz[k], a1.x, gA);
            gB = fma2(qnz[k], b1.x, gB);
            gC = fma2(qnz[k], c1.x, gC);
            gD = fma2(qnz[k], d1.x, gD);
            float alo, ahi, blo, bhi, clo, chi, dlo, dhi;
            unpack2(gA, alo, ahi); unpack2(gB, blo, bhi);
            unpack2(gC, clo, chi); unpack2(gD, dlo, dhi);
            float lo01 = fminf(alo, blo), lo23 = fminf(clo, dlo);
            float hi01 = fminf(ahi, bhi), hi23 = fminf(chi, dhi);
            mn0[k] = fminf(mn0[k], fminf(lo01, lo23));
            mn1[k] = fminf(mn1[k], fminf(hi01, hi23));
        }
    }

    // ---- combine across slices: d2 = 2*g + |q|^2 (>=0), fire-and-forget REDG ----
#pragma unroll
    for (int k = 0; k < 2; k++) {
        float da = fmaxf(fmaf(2.f, mn0[k], x2a[k]), 0.f);
        float db = fmaxf(fmaf(2.f, mn1[k], x2b[k]), 0.f);
        redg_min(g_minbuf + minoff + base + (2 * k) * 256,     __float_as_uint(da));
        redg_min(g_minbuf + minoff + base + (2 * k + 1) * 256, __float_as_uint(db));
    }
}

// ---------------- launch 2: weighted sqrt-sum + fused final (last block) ----
__global__ void k_red(const float* __restrict__ w, float* __restrict__ out,
                      int P, int M, int N) {
    __shared__ float sh[256];
    __shared__ bool last;
    int e = blockIdx.x * 256 + threadIdx.x;   // exactly one element per thread
    int p; float invc;
    if (e < P * M) { p = e / M; invc = 1.0f / (float)M; }
    else           { p = (e - P * M) / N; invc = 1.0f / (float)N; }
    sh[threadIdx.x] = w[p] * invc * sqrtf(__uint_as_float(g_minbuf[e]));
    __syncthreads();
    for (int o = 128; o > 0; o >>= 1) {
        if (threadIdx.x < o) sh[threadIdx.x] += sh[threadIdx.x + o];
        __syncthreads();
    }
    if (threadIdx.x == 0) {
        g_partial[blockIdx.x] = sh[0];
        __threadfence();
        last = (atomicAdd(&g_done, 1u) == NRED - 1);
    }
    __syncthreads();
    if (last) {   // final deterministic tree over 256 partials
        sh[threadIdx.x] = g_partial[threadIdx.x];
        __syncthreads();
        for (int o = 128; o > 0; o >>= 1) {
            if (threadIdx.x < o) sh[threadIdx.x] += sh[threadIdx.x + o];
            __syncthreads();
        }
        if (threadIdx.x == 0) out[0] = sh[0];
    }
}

// ---------------- launcher ----------------------------------------------------
extern "C" void kernel_launch(void* const* d_in, const int* in_sizes, int n_in,
                              void* d_out, int out_size) {
    const float* cam  = (const float*)d_in[0];  // (P,N,3)
    const float* cad  = (const float*)d_in[1];  // (P,M,3)
    const float* wgt  = (const float*)d_in[2];  // (P,)
    const float* quat = (const float*)d_in[3];  // (P,4)
    const float* tra  = (const float*)d_in[4];  // (P,3,1)
    float* out = (float*)d_out;

    int P = in_sizes[2];
    int N = in_sizes[0] / (3 * P);
    int M = in_sizes[1] / (3 * P);
    int write_out = (out_size >= 1 + 16 * P) ? 1 : 0;

    int total = P * (M + N);
    k_prep<<<(total + 255) / 256, 256>>>(cad, cam, quat, tra, out, P, M, N, total, write_out); // 0

    int qcA = (M + QCH - 1) / QCH, tsA = (N + TSL - 1) / TSL;
    int qcB = (N + QCH - 1) / QCH, tsB = (M + TSL - 1) / TSL;
    int items = P * (qcA * tsA + qcB * tsB);   // 4096
    k_chamfer<<<items, 256>>>(P, M, N, qcA, tsA, qcB, tsB);                                    // 1 (hot)

    k_red<<<NRED, 256>>>(wgt, out, P, M, N);                                                   // 2
}